// round 1
// baseline (speedup 1.0000x reference)
#include <cuda_runtime.h>
#include <cuda_bf16.h>
#include <stdint.h>

// ---------------- problem constants ----------------
#define NATOMS   16384
#define NSEL     4096
#define NODE_F   8
#define HID      128
#define HEADS    8
#define DH       16
#define OUTD     256
#define NLIG     32
#define NBINS    65536

typedef unsigned long long ull;

// ---------------- scratch (static device memory; no allocation) ----------------
__device__ float    g_center[3];
__device__ float    g_sq[NATOMS];
__device__ float    g_s0[NATOMS];
__device__ int      g_cnt[NATOMS];
__device__ unsigned g_keys[NATOMS];
__device__ unsigned g_hist[NBINS];
__device__ int      g_H;
__device__ int      g_r;
__device__ int      g_m;
__device__ ull      g_bbuf[NATOMS];
__device__ int      g_sel[NATOMS];
__device__ int      g_bsum[64];
__device__ int      g_boff[64];
__device__ int      g_idx[NSEL];
__device__ float    g_q[NSEL * HID];
__device__ float    g_k[NSEL * HID];
__device__ float    g_v[NSEL * HID];
__device__ float    g_av[NSEL * HID];
__device__ float    g_mav[HID];

// ---------------- 0: zero scratch that is accumulated into ----------------
__global__ void k_zero() {
    int i = blockIdx.x * blockDim.x + threadIdx.x;
    if (i < NBINS) g_hist[i] = 0;
    else if (i < NBINS + NATOMS) g_cnt[i - NBINS] = 0;
    if (i == 0) g_m = 0;
}

// ---------------- 1: ligand center ----------------
__global__ void k_center(const float* __restrict__ lig) {
    int t = threadIdx.x;  // 32 threads
    float x = lig[t * 3 + 0], y = lig[t * 3 + 1], z = lig[t * 3 + 2];
    #pragma unroll
    for (int o = 16; o > 0; o >>= 1) {
        x += __shfl_down_sync(0xFFFFFFFFu, x, o);
        y += __shfl_down_sync(0xFFFFFFFFu, y, o);
        z += __shfl_down_sync(0xFFFFFFFFu, z, o);
    }
    if (t == 0) {
        g_center[0] = x * (1.0f / NLIG);
        g_center[1] = y * (1.0f / NLIG);
        g_center[2] = z * (1.0f / NLIG);
    }
}

// ---------------- 2: per-atom sq norm + ligand-distance score term ----------------
__global__ void k_base(const float* __restrict__ pos) {
    int i = blockIdx.x * blockDim.x + threadIdx.x;
    if (i >= NATOMS) return;
    float x = pos[i * 3 + 0], y = pos[i * 3 + 1], z = pos[i * 3 + 2];
    g_sq[i] = fmaf(z, z, fmaf(y, y, x * x));
    float dx = x - g_center[0], dy = y - g_center[1], dz = z - g_center[2];
    float d = sqrtf(fmaf(dz, dz, fmaf(dy, dy, dx * dx)));
    g_s0[i] = 1.0f / (1.0f + d / 5.0f);
}

// ---------------- 3: brute-force neighbor counting (d2 = sqi+sqj-2*dot < 9) ----------------
__global__ __launch_bounds__(256) void k_neighbor(const float* __restrict__ pos) {
    __shared__ float4 tile[256];
    int tid = threadIdx.x;
    int i = blockIdx.x * 256 + tid;
    float px = pos[i * 3 + 0], py = pos[i * 3 + 1], pz = pos[i * 3 + 2];
    float si = g_sq[i];
    int cnt = 0;
    int j0 = blockIdx.y * 2048;
    for (int jt = 0; jt < 8; jt++) {
        int j = j0 + jt * 256 + tid;
        tile[tid] = make_float4(pos[j * 3 + 0], pos[j * 3 + 1], pos[j * 3 + 2], g_sq[j]);
        __syncthreads();
        #pragma unroll 8
        for (int jj = 0; jj < 256; jj++) {
            float4 T = tile[jj];
            float dot = fmaf(pz, T.z, fmaf(py, T.y, px * T.x));
            float d2  = fmaf(-2.0f, dot, si + T.w);
            cnt += (d2 < 9.0f);
        }
        __syncthreads();
    }
    atomicAdd(&g_cnt[i], cnt);  // integer: deterministic
}

// ---------------- 4: final scores -> sortable keys + histogram ----------------
__global__ void k_scorekey() {
    int i = blockIdx.x * blockDim.x + threadIdx.x;
    if (i >= NATOMS) return;
    // count includes self; neighbor_counts = cnt-1; surface = 1/(nc+1) = 1/cnt
    float surface = 1.0f / (float)g_cnt[i];
    float s = g_s0[i] + 0.5f * surface;          // strictly positive
    unsigned key = __float_as_uint(s);           // monotone for positive floats
    g_keys[i] = key;
    atomicAdd(&g_hist[key >> 16], 1u);
}

// ---------------- 5: find threshold bin H and count r needed from it ----------------
__global__ void k_scan() {
    __shared__ unsigned csum[256];
    int t = threadIdx.x;
    unsigned s = 0;
    for (int b = t * 256; b < (t + 1) * 256; b++) s += g_hist[b];
    csum[t] = s;
    __syncthreads();
    if (t == 0) {
        unsigned g = 0;
        int chunk = 255;
        for (; chunk > 0; chunk--) {
            if (g + csum[chunk] >= (unsigned)NSEL) break;
            g += csum[chunk];
        }
        int H = chunk * 256;
        unsigned r = 1;
        for (int b = chunk * 256 + 255; b >= chunk * 256; b--) {
            unsigned c = g_hist[b];
            if (g + c >= (unsigned)NSEL) { H = b; r = (unsigned)NSEL - g; break; }
            g += c;
        }
        g_H = H;
        g_r = (int)r;
    }
}

// ---------------- 6: collect boundary-bin elements ----------------
__global__ void k_boundary() {
    int i = blockIdx.x * blockDim.x + threadIdx.x;
    if (i >= NATOMS) return;
    unsigned key = g_keys[i];
    if ((int)(key >> 16) == g_H) {
        int p = atomicAdd(&g_m, 1);
        // priority: higher score first, then lower index first
        g_bbuf[p] = ((ull)key << 32) | (ull)(0xFFFFFFFFu - (unsigned)i);
    }
}

// ---------------- 7: selection flags (exact top-k semantics incl. ties) ----------------
__global__ void k_flags() {
    int i = blockIdx.x * blockDim.x + threadIdx.x;
    if (i >= NATOMS) return;
    unsigned key = g_keys[i];
    int hi = (int)(key >> 16);
    int s = 0;
    if (hi > g_H) s = 1;
    else if (hi == g_H) {
        ull mine = ((ull)key << 32) | (ull)(0xFFFFFFFFu - (unsigned)i);
        int m = g_m, cnt = 0, r = g_r;
        for (int t = 0; t < m; t++) cnt += (g_bbuf[t] > mine);
        if (cnt < r) s = 1;
    }
    g_sel[i] = s;
}

// ---------------- 8: deterministic compaction (3 passes) ----------------
__global__ void k_bcount() {
    __shared__ int sm[256];
    int t = threadIdx.x;
    sm[t] = g_sel[blockIdx.x * 256 + t];
    __syncthreads();
    for (int o = 128; o > 0; o >>= 1) {
        if (t < o) sm[t] += sm[t + o];
        __syncthreads();
    }
    if (t == 0) g_bsum[blockIdx.x] = sm[0];
}
__global__ void k_boffsets() {
    if (threadIdx.x == 0) {
        int acc = 0;
        for (int b = 0; b < 64; b++) { g_boff[b] = acc; acc += g_bsum[b]; }
    }
}
__global__ void k_compact() {
    __shared__ int sc[256];
    int t = threadIdx.x;
    int i = blockIdx.x * 256 + t;
    int f = g_sel[i];
    sc[t] = f;
    __syncthreads();
    for (int o = 1; o < 256; o <<= 1) {
        int v = (t >= o) ? sc[t - o] : 0;
        __syncthreads();
        sc[t] += v;
        __syncthreads();
    }
    if (f) g_idx[g_boff[blockIdx.x] + sc[t] - 1] = i;
}

// ---------------- 9: fused gather + node-embed + QKV projection ----------------
__global__ __launch_bounds__(128) void k_qkv(
    const float* __restrict__ x,
    const float* __restrict__ Wn, const float* __restrict__ bn,
    const float* __restrict__ Wq, const float* __restrict__ bq,
    const float* __restrict__ Wk, const float* __restrict__ bk,
    const float* __restrict__ Wv, const float* __restrict__ bv)
{
    __shared__ float hs[4][HID];
    int c = threadIdx.x;
    int r0 = blockIdx.x * 4;
    #pragma unroll
    for (int rr = 0; rr < 4; rr++) {
        int row = g_idx[r0 + rr];
        const float* xr = x + row * NODE_F;
        float acc = bn[c];
        #pragma unroll
        for (int f = 0; f < NODE_F; f++) acc = fmaf(__ldg(xr + f), Wn[f * HID + c], acc);
        hs[rr][c] = acc;
    }
    __syncthreads();
    float aq[4], ak[4], av[4];
    #pragma unroll
    for (int rr = 0; rr < 4; rr++) { aq[rr] = bq[c]; ak[rr] = bk[c]; av[rr] = bv[c]; }
    for (int d = 0; d < HID; d++) {
        float wq = Wq[d * HID + c], wk = Wk[d * HID + c], wv = Wv[d * HID + c];
        #pragma unroll
        for (int rr = 0; rr < 4; rr++) {
            float h = hs[rr][d];
            aq[rr] = fmaf(h, wq, aq[rr]);
            ak[rr] = fmaf(h, wk, ak[rr]);
            av[rr] = fmaf(h, wv, av[rr]);
        }
    }
    #pragma unroll
    for (int rr = 0; rr < 4; rr++) {
        g_q[(r0 + rr) * HID + c] = aq[rr];
        g_k[(r0 + rr) * HID + c] = ak[rr];
        g_v[(r0 + rr) * HID + c] = av[rr];
    }
}

// ---------------- 10: flash-style attention, fp32, no max-subtraction ----------------
// logits ~ N(0,1): exp() cannot overflow fp32; softmax = sum(exp*v)/sum(exp).
__global__ __launch_bounds__(128) void k_attn() {
    __shared__ float4 Ks[128][4];
    __shared__ float4 Vs[128][4];
    int h = blockIdx.y;
    int tid = threadIdx.x;
    int qi = blockIdx.x * 128 + tid;

    const float scale = 0.25f;  // 1/sqrt(16)
    float qv[DH];
    #pragma unroll
    for (int d = 0; d < DH; d++) qv[d] = g_q[qi * HID + h * DH + d] * scale;

    float o[DH];
    #pragma unroll
    for (int d = 0; d < DH; d++) o[d] = 0.0f;
    float l = 0.0f;

    for (int kt = 0; kt < NSEL / 128; kt++) {
        int kr = kt * 128 + tid;
        const float4* kp = (const float4*)&g_k[kr * HID + h * DH];
        const float4* vp = (const float4*)&g_v[kr * HID + h * DH];
        Ks[tid][0] = kp[0]; Ks[tid][1] = kp[1]; Ks[tid][2] = kp[2]; Ks[tid][3] = kp[3];
        Vs[tid][0] = vp[0]; Vs[tid][1] = vp[1]; Vs[tid][2] = vp[2]; Vs[tid][3] = vp[3];
        __syncthreads();
        #pragma unroll 4
        for (int j = 0; j < 128; j++) {
            float4 a = Ks[j][0], b = Ks[j][1], c = Ks[j][2], d4 = Ks[j][3];
            float s;
            s = qv[0] * a.x;
            s = fmaf(qv[1],  a.y, s); s = fmaf(qv[2],  a.z, s); s = fmaf(qv[3],  a.w, s);
            s = fmaf(qv[4],  b.x, s); s = fmaf(qv[5],  b.y, s); s = fmaf(qv[6],  b.z, s);
            s = fmaf(qv[7],  b.w, s); s = fmaf(qv[8],  c.x, s); s = fmaf(qv[9],  c.y, s);
            s = fmaf(qv[10], c.z, s); s = fmaf(qv[11], c.w, s); s = fmaf(qv[12], d4.x, s);
            s = fmaf(qv[13], d4.y, s); s = fmaf(qv[14], d4.z, s); s = fmaf(qv[15], d4.w, s);
            float p = __expf(s);
            l += p;
            float4 va = Vs[j][0], vb = Vs[j][1], vc = Vs[j][2], vd = Vs[j][3];
            o[0]  = fmaf(p, va.x, o[0]);  o[1]  = fmaf(p, va.y, o[1]);
            o[2]  = fmaf(p, va.z, o[2]);  o[3]  = fmaf(p, va.w, o[3]);
            o[4]  = fmaf(p, vb.x, o[4]);  o[5]  = fmaf(p, vb.y, o[5]);
            o[6]  = fmaf(p, vb.z, o[6]);  o[7]  = fmaf(p, vb.w, o[7]);
            o[8]  = fmaf(p, vc.x, o[8]);  o[9]  = fmaf(p, vc.y, o[9]);
            o[10] = fmaf(p, vc.z, o[10]); o[11] = fmaf(p, vc.w, o[11]);
            o[12] = fmaf(p, vd.x, o[12]); o[13] = fmaf(p, vd.y, o[13]);
            o[14] = fmaf(p, vd.z, o[14]); o[15] = fmaf(p, vd.w, o[15]);
        }
        __syncthreads();
    }
    float inv = 1.0f / l;
    #pragma unroll
    for (int d = 0; d < DH; d++) g_av[qi * HID + h * DH + d] = o[d] * inv;
}

// ---------------- 11: deterministic column mean of av ----------------
__global__ void k_colsum() {
    __shared__ float sm[256];
    int col = blockIdx.x;
    int t = threadIdx.x;
    float s = 0.0f;
    for (int r = t; r < NSEL; r += 256) s += g_av[r * HID + col];
    sm[t] = s;
    __syncthreads();
    for (int o = 128; o > 0; o >>= 1) {
        if (t < o) sm[t] += sm[t + o];
        __syncthreads();
    }
    if (t == 0) g_mav[col] = sm[0] * (1.0f / NSEL);
}

// ---------------- 12: Wo + mean-pool commuted + MLP head ----------------
__global__ void k_final(
    const float* __restrict__ Wo, const float* __restrict__ bo,
    const float* __restrict__ W1, const float* __restrict__ b1,
    const float* __restrict__ W2, const float* __restrict__ b2,
    float* __restrict__ out)
{
    __shared__ float mav[HID];
    __shared__ float pooled[HID];
    __shared__ float t1[OUTD];
    int t = threadIdx.x;  // 256 threads
    if (t < HID) mav[t] = g_mav[t];
    __syncthreads();
    if (t < HID) {
        float acc = bo[t];
        for (int d = 0; d < HID; d++) acc = fmaf(mav[d], Wo[d * HID + t], acc);
        pooled[t] = acc;
    }
    __syncthreads();
    {
        float acc = b1[t];
        for (int d = 0; d < HID; d++) acc = fmaf(pooled[d], W1[d * OUTD + t], acc);
        t1[t] = fmaxf(acc, 0.0f);
    }
    __syncthreads();
    {
        float acc = b2[t];
        for (int d = 0; d < OUTD; d++) acc = fmaf(t1[d], W2[d * OUTD + t], acc);
        out[t] = acc;
    }
}

// ---------------- launcher ----------------
extern "C" void kernel_launch(void* const* d_in, const int* in_sizes, int n_in,
                              void* d_out, int out_size)
{
    const float* x    = (const float*)d_in[0];
    const float* pos  = (const float*)d_in[1];
    const float* lig  = (const float*)d_in[2];
    const float* Wn   = (const float*)d_in[3];
    const float* bn   = (const float*)d_in[4];
    const float* Wq   = (const float*)d_in[5];
    const float* bq   = (const float*)d_in[6];
    const float* Wk   = (const float*)d_in[7];
    const float* bk   = (const float*)d_in[8];
    const float* Wv   = (const float*)d_in[9];
    const float* bv   = (const float*)d_in[10];
    const float* Wo   = (const float*)d_in[11];
    const float* bo   = (const float*)d_in[12];
    const float* W1   = (const float*)d_in[13];
    const float* b1   = (const float*)d_in[14];
    const float* W2   = (const float*)d_in[15];
    const float* b2   = (const float*)d_in[16];
    float* out = (float*)d_out;

    k_zero<<<(NBINS + NATOMS + 255) / 256, 256>>>();
    k_center<<<1, 32>>>(lig);
    k_base<<<NATOMS / 256, 256>>>(pos);
    k_neighbor<<<dim3(NATOMS / 256, 8), 256>>>(pos);
    k_scorekey<<<NATOMS / 256, 256>>>();
    k_scan<<<1, 256>>>();
    k_boundary<<<NATOMS / 256, 256>>>();
    k_flags<<<NATOMS / 256, 256>>>();
    k_bcount<<<64, 256>>>();
    k_boffsets<<<1, 32>>>();
    k_compact<<<64, 256>>>();
    k_qkv<<<NSEL / 4, 128>>>(x, Wn, bn, Wq, bq, Wk, bk, Wv, bv);
    k_attn<<<dim3(NSEL / 128, HEADS), 128>>>();
    k_colsum<<<HID, 256>>>();
    k_final<<<1, 256>>>(Wo, bo, W1, b1, W2, b2, out);
}

// round 2
// speedup vs baseline: 1.0002x; 1.0002x over previous
#include <cuda_runtime.h>
#include <cuda_bf16.h>
#include <stdint.h>

// ---------------- problem constants ----------------
#define NATOMS   16384
#define NSEL     4096
#define NODE_F   8
#define HID      128
#define HEADS    8
#define DH       16
#define OUTD     256
#define NLIG     32
#define NBINS    65536

typedef unsigned long long ull;

// ---------------- scratch (static device memory; no allocation) ----------------
__device__ float    g_center[3];
__device__ float    g_sq[NATOMS];
__device__ float    g_s0[NATOMS];
__device__ int      g_cnt[NATOMS];
__device__ unsigned g_keys[NATOMS];
__device__ unsigned g_hist[NBINS];
__device__ int      g_H;
__device__ int      g_r;
__device__ int      g_m;
__device__ ull      g_bbuf[NATOMS];
__device__ int      g_sel[NATOMS];
__device__ int      g_bsum[64];
__device__ int      g_boff[64];
__device__ int      g_idx[NSEL];
__device__ float    g_q[NSEL * HID];
__device__ float    g_k[NSEL * HID];
__device__ float    g_v[NSEL * HID];
__device__ float    g_av[NSEL * HID];
__device__ float    g_mav[HID];

// ---------------- 0: zero scratch that is accumulated into ----------------
__global__ void k_zero() {
    int i = blockIdx.x * blockDim.x + threadIdx.x;
    if (i < NBINS) g_hist[i] = 0;
    else if (i < NBINS + NATOMS) g_cnt[i - NBINS] = 0;
    if (i == 0) g_m = 0;
}

// ---------------- 1: ligand center ----------------
__global__ void k_center(const float* __restrict__ lig) {
    int t = threadIdx.x;  // 32 threads
    float x = lig[t * 3 + 0], y = lig[t * 3 + 1], z = lig[t * 3 + 2];
    #pragma unroll
    for (int o = 16; o > 0; o >>= 1) {
        x += __shfl_down_sync(0xFFFFFFFFu, x, o);
        y += __shfl_down_sync(0xFFFFFFFFu, y, o);
        z += __shfl_down_sync(0xFFFFFFFFu, z, o);
    }
    if (t == 0) {
        g_center[0] = x * (1.0f / NLIG);
        g_center[1] = y * (1.0f / NLIG);
        g_center[2] = z * (1.0f / NLIG);
    }
}

// ---------------- 2: per-atom sq norm + ligand-distance score term ----------------
__global__ void k_base(const float* __restrict__ pos) {
    int i = blockIdx.x * blockDim.x + threadIdx.x;
    if (i >= NATOMS) return;
    float x = pos[i * 3 + 0], y = pos[i * 3 + 1], z = pos[i * 3 + 2];
    g_sq[i] = fmaf(z, z, fmaf(y, y, x * x));
    float dx = x - g_center[0], dy = y - g_center[1], dz = z - g_center[2];
    float d = sqrtf(fmaf(dz, dz, fmaf(dy, dy, dx * dx)));
    g_s0[i] = 1.0f / (1.0f + d / 5.0f);
}

// ---------------- 3: brute-force neighbor counting (d2 = sqi+sqj-2*dot < 9) ----------------
__global__ __launch_bounds__(256) void k_neighbor(const float* __restrict__ pos) {
    __shared__ float4 tile[256];
    int tid = threadIdx.x;
    int i = blockIdx.x * 256 + tid;
    float px = pos[i * 3 + 0], py = pos[i * 3 + 1], pz = pos[i * 3 + 2];
    float si = g_sq[i];
    int cnt = 0;
    int j0 = blockIdx.y * 2048;
    for (int jt = 0; jt < 8; jt++) {
        int j = j0 + jt * 256 + tid;
        tile[tid] = make_float4(pos[j * 3 + 0], pos[j * 3 + 1], pos[j * 3 + 2], g_sq[j]);
        __syncthreads();
        #pragma unroll 8
        for (int jj = 0; jj < 256; jj++) {
            float4 T = tile[jj];
            float dot = fmaf(pz, T.z, fmaf(py, T.y, px * T.x));
            float d2  = fmaf(-2.0f, dot, si + T.w);
            cnt += (d2 < 9.0f);
        }
        __syncthreads();
    }
    atomicAdd(&g_cnt[i], cnt);  // integer: deterministic
}

// ---------------- 4: final scores -> sortable keys + histogram ----------------
__global__ void k_scorekey() {
    int i = blockIdx.x * blockDim.x + threadIdx.x;
    if (i >= NATOMS) return;
    // count includes self; neighbor_counts = cnt-1; surface = 1/(nc+1) = 1/cnt
    float surface = 1.0f / (float)g_cnt[i];
    float s = g_s0[i] + 0.5f * surface;          // strictly positive
    unsigned key = __float_as_uint(s);           // monotone for positive floats
    g_keys[i] = key;
    atomicAdd(&g_hist[key >> 16], 1u);
}

// ---------------- 5: find threshold bin H and count r needed from it ----------------
__global__ void k_scan() {
    __shared__ unsigned csum[256];
    int t = threadIdx.x;
    unsigned s = 0;
    for (int b = t * 256; b < (t + 1) * 256; b++) s += g_hist[b];
    csum[t] = s;
    __syncthreads();
    if (t == 0) {
        unsigned g = 0;
        int chunk = 255;
        for (; chunk > 0; chunk--) {
            if (g + csum[chunk] >= (unsigned)NSEL) break;
            g += csum[chunk];
        }
        int H = chunk * 256;
        unsigned r = 1;
        for (int b = chunk * 256 + 255; b >= chunk * 256; b--) {
            unsigned c = g_hist[b];
            if (g + c >= (unsigned)NSEL) { H = b; r = (unsigned)NSEL - g; break; }
            g += c;
        }
        g_H = H;
        g_r = (int)r;
    }
}

// ---------------- 6: collect boundary-bin elements ----------------
__global__ void k_boundary() {
    int i = blockIdx.x * blockDim.x + threadIdx.x;
    if (i >= NATOMS) return;
    unsigned key = g_keys[i];
    if ((int)(key >> 16) == g_H) {
        int p = atomicAdd(&g_m, 1);
        // priority: higher score first, then lower index first
        g_bbuf[p] = ((ull)key << 32) | (ull)(0xFFFFFFFFu - (unsigned)i);
    }
}

// ---------------- 7: selection flags (exact top-k semantics incl. ties) ----------------
__global__ void k_flags() {
    int i = blockIdx.x * blockDim.x + threadIdx.x;
    if (i >= NATOMS) return;
    unsigned key = g_keys[i];
    int hi = (int)(key >> 16);
    int s = 0;
    if (hi > g_H) s = 1;
    else if (hi == g_H) {
        ull mine = ((ull)key << 32) | (ull)(0xFFFFFFFFu - (unsigned)i);
        int m = g_m, cnt = 0, r = g_r;
        for (int t = 0; t < m; t++) cnt += (g_bbuf[t] > mine);
        if (cnt < r) s = 1;
    }
    g_sel[i] = s;
}

// ---------------- 8: deterministic compaction (3 passes) ----------------
__global__ void k_bcount() {
    __shared__ int sm[256];
    int t = threadIdx.x;
    sm[t] = g_sel[blockIdx.x * 256 + t];
    __syncthreads();
    for (int o = 128; o > 0; o >>= 1) {
        if (t < o) sm[t] += sm[t + o];
        __syncthreads();
    }
    if (t == 0) g_bsum[blockIdx.x] = sm[0];
}
__global__ void k_boffsets() {
    if (threadIdx.x == 0) {
        int acc = 0;
        for (int b = 0; b < 64; b++) { g_boff[b] = acc; acc += g_bsum[b]; }
    }
}
__global__ void k_compact() {
    __shared__ int sc[256];
    int t = threadIdx.x;
    int i = blockIdx.x * 256 + t;
    int f = g_sel[i];
    sc[t] = f;
    __syncthreads();
    for (int o = 1; o < 256; o <<= 1) {
        int v = (t >= o) ? sc[t - o] : 0;
        __syncthreads();
        sc[t] += v;
        __syncthreads();
    }
    if (f) g_idx[g_boff[blockIdx.x] + sc[t] - 1] = i;
}

// ---------------- 9: fused gather + node-embed + QKV projection ----------------
__global__ __launch_bounds__(128) void k_qkv(
    const float* __restrict__ x,
    const float* __restrict__ Wn, const float* __restrict__ bn,
    const float* __restrict__ Wq, const float* __restrict__ bq,
    const float* __restrict__ Wk, const float* __restrict__ bk,
    const float* __restrict__ Wv, const float* __restrict__ bv)
{
    __shared__ float hs[4][HID];
    int c = threadIdx.x;
    int r0 = blockIdx.x * 4;
    #pragma unroll
    for (int rr = 0; rr < 4; rr++) {
        int row = g_idx[r0 + rr];
        const float* xr = x + row * NODE_F;
        float acc = bn[c];
        #pragma unroll
        for (int f = 0; f < NODE_F; f++) acc = fmaf(__ldg(xr + f), Wn[f * HID + c], acc);
        hs[rr][c] = acc;
    }
    __syncthreads();
    float aq[4], ak[4], av[4];
    #pragma unroll
    for (int rr = 0; rr < 4; rr++) { aq[rr] = bq[c]; ak[rr] = bk[c]; av[rr] = bv[c]; }
    for (int d = 0; d < HID; d++) {
        float wq = Wq[d * HID + c], wk = Wk[d * HID + c], wv = Wv[d * HID + c];
        #pragma unroll
        for (int rr = 0; rr < 4; rr++) {
            float h = hs[rr][d];
            aq[rr] = fmaf(h, wq, aq[rr]);
            ak[rr] = fmaf(h, wk, ak[rr]);
            av[rr] = fmaf(h, wv, av[rr]);
        }
    }
    #pragma unroll
    for (int rr = 0; rr < 4; rr++) {
        g_q[(r0 + rr) * HID + c] = aq[rr];
        g_k[(r0 + rr) * HID + c] = ak[rr];
        g_v[(r0 + rr) * HID + c] = av[rr];
    }
}

// ---------------- 10: flash-style attention, fp32, no max-subtraction ----------------
// logits ~ N(0,1): exp() cannot overflow fp32; softmax = sum(exp*v)/sum(exp).
__global__ __launch_bounds__(128) void k_attn() {
    __shared__ float4 Ks[128][4];
    __shared__ float4 Vs[128][4];
    int h = blockIdx.y;
    int tid = threadIdx.x;
    int qi = blockIdx.x * 128 + tid;

    const float scale = 0.25f;  // 1/sqrt(16)
    float qv[DH];
    #pragma unroll
    for (int d = 0; d < DH; d++) qv[d] = g_q[qi * HID + h * DH + d] * scale;

    float o[DH];
    #pragma unroll
    for (int d = 0; d < DH; d++) o[d] = 0.0f;
    float l = 0.0f;

    for (int kt = 0; kt < NSEL / 128; kt++) {
        int kr = kt * 128 + tid;
        const float4* kp = (const float4*)&g_k[kr * HID + h * DH];
        const float4* vp = (const float4*)&g_v[kr * HID + h * DH];
        Ks[tid][0] = kp[0]; Ks[tid][1] = kp[1]; Ks[tid][2] = kp[2]; Ks[tid][3] = kp[3];
        Vs[tid][0] = vp[0]; Vs[tid][1] = vp[1]; Vs[tid][2] = vp[2]; Vs[tid][3] = vp[3];
        __syncthreads();
        #pragma unroll 4
        for (int j = 0; j < 128; j++) {
            float4 a = Ks[j][0], b = Ks[j][1], c = Ks[j][2], d4 = Ks[j][3];
            float s;
            s = qv[0] * a.x;
            s = fmaf(qv[1],  a.y, s); s = fmaf(qv[2],  a.z, s); s = fmaf(qv[3],  a.w, s);
            s = fmaf(qv[4],  b.x, s); s = fmaf(qv[5],  b.y, s); s = fmaf(qv[6],  b.z, s);
            s = fmaf(qv[7],  b.w, s); s = fmaf(qv[8],  c.x, s); s = fmaf(qv[9],  c.y, s);
            s = fmaf(qv[10], c.z, s); s = fmaf(qv[11], c.w, s); s = fmaf(qv[12], d4.x, s);
            s = fmaf(qv[13], d4.y, s); s = fmaf(qv[14], d4.z, s); s = fmaf(qv[15], d4.w, s);
            float p = __expf(s);
            l += p;
            float4 va = Vs[j][0], vb = Vs[j][1], vc = Vs[j][2], vd = Vs[j][3];
            o[0]  = fmaf(p, va.x, o[0]);  o[1]  = fmaf(p, va.y, o[1]);
            o[2]  = fmaf(p, va.z, o[2]);  o[3]  = fmaf(p, va.w, o[3]);
            o[4]  = fmaf(p, vb.x, o[4]);  o[5]  = fmaf(p, vb.y, o[5]);
            o[6]  = fmaf(p, vb.z, o[6]);  o[7]  = fmaf(p, vb.w, o[7]);
            o[8]  = fmaf(p, vc.x, o[8]);  o[9]  = fmaf(p, vc.y, o[9]);
            o[10] = fmaf(p, vc.z, o[10]); o[11] = fmaf(p, vc.w, o[11]);
            o[12] = fmaf(p, vd.x, o[12]); o[13] = fmaf(p, vd.y, o[13]);
            o[14] = fmaf(p, vd.z, o[14]); o[15] = fmaf(p, vd.w, o[15]);
        }
        __syncthreads();
    }
    float inv = 1.0f / l;
    #pragma unroll
    for (int d = 0; d < DH; d++) g_av[qi * HID + h * DH + d] = o[d] * inv;
}

// ---------------- 11: deterministic column mean of av ----------------
__global__ void k_colsum() {
    __shared__ float sm[256];
    int col = blockIdx.x;
    int t = threadIdx.x;
    float s = 0.0f;
    for (int r = t; r < NSEL; r += 256) s += g_av[r * HID + col];
    sm[t] = s;
    __syncthreads();
    for (int o = 128; o > 0; o >>= 1) {
        if (t < o) sm[t] += sm[t + o];
        __syncthreads();
    }
    if (t == 0) g_mav[col] = sm[0] * (1.0f / NSEL);
}

// ---------------- 12: Wo + mean-pool commuted + MLP head ----------------
__global__ void k_final(
    const float* __restrict__ Wo, const float* __restrict__ bo,
    const float* __restrict__ W1, const float* __restrict__ b1,
    const float* __restrict__ W2, const float* __restrict__ b2,
    float* __restrict__ out)
{
    __shared__ float mav[HID];
    __shared__ float pooled[HID];
    __shared__ float t1[OUTD];
    int t = threadIdx.x;  // 256 threads
    if (t < HID) mav[t] = g_mav[t];
    __syncthreads();
    if (t < HID) {
        float acc = bo[t];
        for (int d = 0; d < HID; d++) acc = fmaf(mav[d], Wo[d * HID + t], acc);
        pooled[t] = acc;
    }
    __syncthreads();
    {
        float acc = b1[t];
        for (int d = 0; d < HID; d++) acc = fmaf(pooled[d], W1[d * OUTD + t], acc);
        t1[t] = fmaxf(acc, 0.0f);
    }
    __syncthreads();
    {
        float acc = b2[t];
        for (int d = 0; d < OUTD; d++) acc = fmaf(t1[d], W2[d * OUTD + t], acc);
        out[t] = acc;
    }
}

// ---------------- launcher ----------------
extern "C" void kernel_launch(void* const* d_in, const int* in_sizes, int n_in,
                              void* d_out, int out_size)
{
    const float* x    = (const float*)d_in[0];
    const float* pos  = (const float*)d_in[1];
    const float* lig  = (const float*)d_in[2];
    const float* Wn   = (const float*)d_in[3];
    const float* bn   = (const float*)d_in[4];
    const float* Wq   = (const float*)d_in[5];
    const float* bq   = (const float*)d_in[6];
    const float* Wk   = (const float*)d_in[7];
    const float* bk   = (const float*)d_in[8];
    const float* Wv   = (const float*)d_in[9];
    const float* bv   = (const float*)d_in[10];
    const float* Wo   = (const float*)d_in[11];
    const float* bo   = (const float*)d_in[12];
    const float* W1   = (const float*)d_in[13];
    const float* b1   = (const float*)d_in[14];
    const float* W2   = (const float*)d_in[15];
    const float* b2   = (const float*)d_in[16];
    float* out = (float*)d_out;

    k_zero<<<(NBINS + NATOMS + 255) / 256, 256>>>();
    k_center<<<1, 32>>>(lig);
    k_base<<<NATOMS / 256, 256>>>(pos);
    k_neighbor<<<dim3(NATOMS / 256, 8), 256>>>(pos);
    k_scorekey<<<NATOMS / 256, 256>>>();
    k_scan<<<1, 256>>>();
    k_boundary<<<NATOMS / 256, 256>>>();
    k_flags<<<NATOMS / 256, 256>>>();
    k_bcount<<<64, 256>>>();
    k_boffsets<<<1, 32>>>();
    k_compact<<<64, 256>>>();
    k_qkv<<<NSEL / 4, 128>>>(x, Wn, bn, Wq, bq, Wk, bk, Wv, bv);
    k_attn<<<dim3(NSEL / 128, HEADS), 128>>>();
    k_colsum<<<HID, 256>>>();
    k_final<<<1, 256>>>(Wo, bo, W1, b1, W2, b2, out);
}